// round 3
// baseline (speedup 1.0000x reference)
#include <cuda_runtime.h>

#define NN   16384
#define EE   524288
#define FIN  128
#define FHID 256
#define FOUT 128
#define LN_EPS 1e-5f

// ---------------- static device scratch (allowed; allocated at module load) ----
__device__ unsigned int g_slot[(size_t)NN * NN];   // 1 GB dedup table, zero-init, restored each run
__device__ float g_deg[NN];
__device__ int   g_cnt[NN];
__device__ int   g_rowptr[NN + 1];
__device__ int   g_cursor[NN];
__device__ int   g_col[EE];
__device__ float g_wgt[EE];
__device__ float g_agg[(size_t)NN * FIN];
__device__ float g_h[(size_t)NN * FHID];
__device__ float g_z[(size_t)NN * FOUT];
__device__ int   g_is64;

// ---------------- edge index dtype detection (int64 vs int32) -----------------
__global__ void k_detect(const void* __restrict__ ei) {
    const int* p = (const int*)ei;
    int o = 0;
#pragma unroll
    for (int i = 0; i < 64; i++) o |= p[2 * i + 1];
    // values are in [0, 16384): if stored as int64, every high word is 0.
    g_is64 = (o == 0) ? 1 : 0;
}

__device__ __forceinline__ void load_edge(const void* __restrict__ ei, int e,
                                          unsigned& r, unsigned& c) {
    if (g_is64) {
        const long long* p = (const long long*)ei;
        r = (unsigned)p[e];
        c = (unsigned)p[EE + e];
    } else {
        const int* p = (const int*)ei;
        r = (unsigned)p[e];
        c = (unsigned)p[EE + e];
    }
}

// ---------------- CSR build with last-write-wins dedup -------------------------
__global__ void k_init() {
    int i = blockIdx.x * blockDim.x + threadIdx.x;
    if (i < NN) { g_deg[i] = 1.0f; g_cnt[i] = 0; }
}

__global__ void k_scatter(const void* __restrict__ ei) {
    int e = blockIdx.x * blockDim.x + threadIdx.x;
    if (e >= EE) return;
    unsigned r, c;
    load_edge(ei, e, r, c);
    atomicMax(&g_slot[((size_t)r << 14) + c], (unsigned)(e + 1));
}

__global__ void k_count(const void* __restrict__ ei, const float* __restrict__ ew) {
    int e = blockIdx.x * blockDim.x + threadIdx.x;
    if (e >= EE) return;
    unsigned r, c;
    load_edge(ei, e, r, c);
    if (g_slot[((size_t)r << 14) + c] == (unsigned)(e + 1)) {
        atomicAdd(&g_cnt[r], 1);
        atomicAdd(&g_deg[r], ew[e]);
    }
}

// one block, 1024 threads, 16 rows per thread: exclusive prefix over g_cnt
__global__ void k_scan() {
    __shared__ int sm[1024];
    int tid = threadIdx.x;
    int base = tid * 16;
    int loc[16];
    int run = 0;
#pragma unroll
    for (int i = 0; i < 16; i++) { loc[i] = run; run += g_cnt[base + i]; }
    sm[tid] = run;
    __syncthreads();
    for (int off = 1; off < 1024; off <<= 1) {
        int v = (tid >= off) ? sm[tid - off] : 0;
        __syncthreads();
        sm[tid] += v;
        __syncthreads();
    }
    int excl = (tid == 0) ? 0 : sm[tid - 1];
#pragma unroll
    for (int i = 0; i < 16; i++) {
        int p = excl + loc[i];
        g_rowptr[base + i] = p;
        g_cursor[base + i] = p;
    }
    if (tid == 1023) g_rowptr[NN] = sm[1023];
}

__global__ void k_fill(const void* __restrict__ ei, const float* __restrict__ ew) {
    int e = blockIdx.x * blockDim.x + threadIdx.x;
    if (e >= EE) return;
    unsigned r, c;
    load_edge(ei, e, r, c);
    size_t key = ((size_t)r << 14) + c;
    if (g_slot[key] == (unsigned)(e + 1)) {
        int p = atomicAdd(&g_cursor[r], 1);
        g_col[p] = (int)c;
        g_wgt[p] = ew[e];
        g_slot[key] = 0u;   // restore invariant for graph replay (one winner per touched key)
    }
}

// ---------------- SpMM: warp per row, float4 per lane (F=128) ------------------
__global__ void k_spmm1(const float* __restrict__ Xf) {
    int g = blockIdx.x * blockDim.x + threadIdx.x;
    int row = g >> 5, lane = g & 31;
    const float4* __restrict__ X = (const float4*)Xf;
    float inv = 1.0f / g_deg[row];
    float4 a = X[((size_t)row << 5) + lane];
    float4 acc = make_float4(a.x * inv, a.y * inv, a.z * inv, a.w * inv);
    int s = g_rowptr[row], t = g_rowptr[row + 1];
    for (int j = s; j < t; j++) {
        int   c = __ldg(&g_col[j]);
        float w = __ldg(&g_wgt[j]) * inv;
        float4 v = X[((size_t)c << 5) + lane];
        acc.x += w * v.x; acc.y += w * v.y; acc.z += w * v.z; acc.w += w * v.w;
    }
    ((float4*)g_agg)[((size_t)row << 5) + lane] = acc;
}

__global__ void k_spmm2(const float* __restrict__ b2, float* __restrict__ outf) {
    int g = blockIdx.x * blockDim.x + threadIdx.x;
    int row = g >> 5, lane = g & 31;
    const float4* __restrict__ X = (const float4*)g_z;
    float inv = 1.0f / g_deg[row];
    float4 a = X[((size_t)row << 5) + lane];
    float4 acc = make_float4(a.x * inv, a.y * inv, a.z * inv, a.w * inv);
    int s = g_rowptr[row], t = g_rowptr[row + 1];
    for (int j = s; j < t; j++) {
        int   c = __ldg(&g_col[j]);
        float w = __ldg(&g_wgt[j]) * inv;
        float4 v = X[((size_t)c << 5) + lane];
        acc.x += w * v.x; acc.y += w * v.y; acc.z += w * v.z; acc.w += w * v.w;
    }
    float4 bb = ((const float4*)b2)[lane];
    acc.x += bb.x; acc.y += bb.y; acc.z += bb.z; acc.w += bb.w;
    ((float4*)outf)[((size_t)row << 5) + lane] = acc;
}

#define COMP(v, kk) ((kk) == 0 ? (v).x : (kk) == 1 ? (v).y : (kk) == 2 ? (v).z : (v).w)

// ---------------- GEMM1 fused: h = relu(LN(agg @ W1 + b1)) --------------------
// block: 64 rows x 256 cols, 256 threads, thread tile 8x8.
// warp w owns rows [8w..8w+8); its 32 lanes cover all 256 cols -> LN is a warp reduce.
#define G1_SMEM ((FIN * FHID + 64 * FIN) * 4)
__global__ void __launch_bounds__(256, 1)
k_g1(const float* __restrict__ W1, const float* __restrict__ b1,
     const float* __restrict__ lng, const float* __restrict__ lnb) {
    extern __shared__ float sm[];
    float4* Bs4 = (float4*)sm;                 // 128x256 -> 8192 float4
    float4* As4 = (float4*)(sm + FIN * FHID);  // 64x128  -> 2048 float4
    const int tid = threadIdx.x;
    const int rbase = blockIdx.x * 64;

    const float4* Wg = (const float4*)W1;
#pragma unroll
    for (int i = 0; i < 32; i++) Bs4[tid + i * 256] = Wg[tid + i * 256];
    const float4* Ag = (const float4*)(g_agg + (size_t)rbase * FIN);
#pragma unroll
    for (int i = 0; i < 8; i++) As4[tid + i * 256] = Ag[tid + i * 256];
    __syncthreads();

    const int cc = tid & 31, rr = tid >> 5;
    float acc[8][8];
#pragma unroll
    for (int i = 0; i < 8; i++)
#pragma unroll
        for (int j = 0; j < 8; j++) acc[i][j] = 0.f;

    for (int k4 = 0; k4 < FIN / 4; k4++) {
        float4 av[8];
#pragma unroll
        for (int i = 0; i < 8; i++) av[i] = As4[(rr * 8 + i) * 32 + k4];
#pragma unroll
        for (int kk = 0; kk < 4; kk++) {
            const int k = k4 * 4 + kk;
            float4 b0 = Bs4[k * 64 + cc * 2];
            float4 b1v = Bs4[k * 64 + cc * 2 + 1];
#pragma unroll
            for (int i = 0; i < 8; i++) {
                float a = COMP(av[i], kk);
                acc[i][0] += a * b0.x;  acc[i][1] += a * b0.y;
                acc[i][2] += a * b0.z;  acc[i][3] += a * b0.w;
                acc[i][4] += a * b1v.x; acc[i][5] += a * b1v.y;
                acc[i][6] += a * b1v.z; acc[i][7] += a * b1v.w;
            }
        }
    }

    float4 bb0 = ((const float4*)b1)[cc * 2],  bb1 = ((const float4*)b1)[cc * 2 + 1];
    float4 gg0 = ((const float4*)lng)[cc * 2], gg1 = ((const float4*)lng)[cc * 2 + 1];
    float4 nb0 = ((const float4*)lnb)[cc * 2], nb1 = ((const float4*)lnb)[cc * 2 + 1];
    float4* H4 = (float4*)g_h;
#pragma unroll
    for (int i = 0; i < 8; i++) {
        float v0 = acc[i][0] + bb0.x, v1 = acc[i][1] + bb0.y;
        float v2 = acc[i][2] + bb0.z, v3 = acc[i][3] + bb0.w;
        float v4 = acc[i][4] + bb1.x, v5 = acc[i][5] + bb1.y;
        float v6 = acc[i][6] + bb1.z, v7 = acc[i][7] + bb1.w;
        float s = v0 + v1 + v2 + v3 + v4 + v5 + v6 + v7;
        float q = v0 * v0 + v1 * v1 + v2 * v2 + v3 * v3 +
                  v4 * v4 + v5 * v5 + v6 * v6 + v7 * v7;
#pragma unroll
        for (int off = 16; off > 0; off >>= 1) {
            s += __shfl_xor_sync(0xffffffffu, s, off);
            q += __shfl_xor_sync(0xffffffffu, q, off);
        }
        float mu  = s * (1.0f / FHID);
        float var = q * (1.0f / FHID) - mu * mu;
        float rstd = rsqrtf(var + LN_EPS);
        float o0 = fmaxf((v0 - mu) * rstd * gg0.x + nb0.x, 0.f);
        float o1 = fmaxf((v1 - mu) * rstd * gg0.y + nb0.y, 0.f);
        float o2 = fmaxf((v2 - mu) * rstd * gg0.z + nb0.z, 0.f);
        float o3 = fmaxf((v3 - mu) * rstd * gg0.w + nb0.w, 0.f);
        float o4 = fmaxf((v4 - mu) * rstd * gg1.x + nb1.x, 0.f);
        float o5 = fmaxf((v5 - mu) * rstd * gg1.y + nb1.y, 0.f);
        float o6 = fmaxf((v6 - mu) * rstd * gg1.z + nb1.z, 0.f);
        float o7 = fmaxf((v7 - mu) * rstd * gg1.w + nb1.w, 0.f);
        size_t row = (size_t)(rbase + rr * 8 + i);
        H4[row * 64 + cc * 2]     = make_float4(o0, o1, o2, o3);
        H4[row * 64 + cc * 2 + 1] = make_float4(o4, o5, o6, o7);
    }
}

// ---------------- GEMM2: z = h @ W2 (bias folded into SpMM2) -------------------
// block: 64 rows x 128 cols, 256 threads, thread tile 8x4.
#define G2_SMEM ((FHID * FOUT + 64 * FHID) * 4)
__global__ void __launch_bounds__(256, 1)
k_g2(const float* __restrict__ W2) {
    extern __shared__ float sm[];
    float4* Bs4 = (float4*)sm;                  // 256x128 -> 8192 float4
    float4* As4 = (float4*)(sm + FHID * FOUT);  // 64x256  -> 4096 float4
    const int tid = threadIdx.x;
    const int rbase = blockIdx.x * 64;

    const float4* Wg = (const float4*)W2;
#pragma unroll
    for (int i = 0; i < 32; i++) Bs4[tid + i * 256] = Wg[tid + i * 256];
    const float4* Hg = (const float4*)(g_h + (size_t)rbase * FHID);
#pragma unroll
    for (int i = 0; i < 16; i++) As4[tid + i * 256] = Hg[tid + i * 256];
    __syncthreads();

    const int cc = tid & 31, rr = tid >> 5;
    float acc[8][4];
#pragma unroll
    for (int i = 0; i < 8; i++)
#pragma unroll
        for (int j = 0; j < 4; j++) acc[i][j] = 0.f;

    for (int k4 = 0; k4 < FHID / 4; k4++) {
        float4 av[8];
#pragma unroll
        for (int i = 0; i < 8; i++) av[i] = As4[(rr * 8 + i) * 64 + k4];
#pragma unroll
        for (int kk = 0; kk < 4; kk++) {
            const int k = k4 * 4 + kk;
            float4 bv = Bs4[k * 32 + cc];
#pragma unroll
            for (int i = 0; i < 8; i++) {
                float a = COMP(av[i], kk);
                acc[i][0] += a * bv.x; acc[i][1] += a * bv.y;
                acc[i][2] += a * bv.z; acc[i][3] += a * bv.w;
            }
        }
    }

    float4* Z = (float4*)g_z;
#pragma unroll
    for (int i = 0; i < 8; i++) {
        size_t row = (size_t)(rbase + rr * 8 + i);
        Z[row * 32 + cc] = make_float4(acc[i][0], acc[i][1], acc[i][2], acc[i][3]);
    }
}

// ---------------- launch ------------------------------------------------------
extern "C" void kernel_launch(void* const* d_in, const int* in_sizes, int n_in,
                              void* d_out, int out_size) {
    const float* x   = (const float*)d_in[0];
    const void*  ei  = d_in[1];
    const float* ew  = (const float*)d_in[2];
    const float* W1  = (const float*)d_in[3];
    const float* b1  = (const float*)d_in[4];
    const float* W2  = (const float*)d_in[5];
    const float* b2  = (const float*)d_in[6];
    const float* lng = (const float*)d_in[7];
    const float* lnb = (const float*)d_in[8];
    float* out = (float*)d_out;

    cudaFuncSetAttribute(k_g1, cudaFuncAttributeMaxDynamicSharedMemorySize, G1_SMEM);
    cudaFuncSetAttribute(k_g2, cudaFuncAttributeMaxDynamicSharedMemorySize, G2_SMEM);

    k_detect<<<1, 1>>>(ei);
    k_init<<<NN / 256, 256>>>();
    k_scatter<<<EE / 256, 256>>>(ei);
    k_count<<<EE / 256, 256>>>(ei, ew);
    k_scan<<<1, 1024>>>();
    k_fill<<<EE / 256, 256>>>(ei, ew);
    k_spmm1<<<(NN * 32) / 256, 256>>>(x);
    k_g1<<<NN / 64, 256, G1_SMEM>>>(W1, b1, lng, lnb);
    k_g2<<<NN / 64, 256, G2_SMEM>>>(W2);
    k_spmm2<<<(NN * 32) / 256, 256>>>(b2, out);
}

// round 4
// speedup vs baseline: 1.1627x; 1.1627x over previous
#include <cuda_runtime.h>
#include <cuda_fp16.h>

#define NN   16384
#define EE   524288
#define FIN  128
#define FHID 256
#define FOUT 128
#define LN_EPS 1e-5f

typedef unsigned long long u64t;

// ---------------- static device scratch ----------------------------------------
__device__ unsigned g_bm[1u << 23];          // 2^28-bit dedup bitmap = 32 MB (L2-resident)
#define HSZ 16384
#define HEMPTY 0xFFFFFFFFu
__device__ unsigned g_hkey[HSZ];             // conflict hash: keys
__device__ unsigned g_hmax[HSZ];             // conflict hash: max (e+1) per key
__device__ int      g_nconf;
#define MAXCONF 32768
__device__ unsigned g_confkey[MAXCONF];

__device__ float g_deg[NN];
__device__ int   g_cnt[NN];
__device__ int   g_rowptr[NN + 1];
__device__ int   g_cursor[NN];
__device__ int   g_col[EE];
__device__ float g_wgt[EE];
__device__ float g_agg[(size_t)NN * FIN];
__device__ float g_h[(size_t)NN * FHID];
__device__ __half2 g_xh[(size_t)NN * FIN / 2];   // x in fp16 for SpMM1 gather
__device__ __half2 g_zh[(size_t)NN * FOUT / 2];  // h@W2 in fp16 for SpMM2 gather
__device__ int   g_is64;

__device__ __forceinline__ unsigned hsh(unsigned k) {
    return ((k * 2654435761u) >> 14) & (HSZ - 1);
}

// ---------------- f32x2 packed-FMA helpers (PTX-only on sm_103a) ---------------
__device__ __forceinline__ u64t pk2(float x, float y) {
    u64t r;
    asm("mov.b64 %0, {%1, %2};" : "=l"(r) : "r"(__float_as_uint(x)), "r"(__float_as_uint(y)));
    return r;
}
__device__ __forceinline__ void unpk(u64t v, float& x, float& y) {
    unsigned a, b;
    asm("mov.b64 {%0, %1}, %2;" : "=r"(a), "=r"(b) : "l"(v));
    x = __uint_as_float(a); y = __uint_as_float(b);
}
__device__ __forceinline__ void ffma2(u64t& d, u64t a, u64t b) {
    asm("fma.rn.f32x2 %0, %1, %2, %3;" : "=l"(d) : "l"(a), "l"(b), "l"(d));
}

// ---------------- edge index dtype detection -----------------------------------
__global__ void k_detect(const void* __restrict__ ei) {
    const int* p = (const int*)ei;
    int o = 0;
#pragma unroll
    for (int i = 0; i < 64; i++) o |= p[2 * i + 1];
    g_is64 = (o == 0) ? 1 : 0;
}

__device__ __forceinline__ void load_edge(const void* __restrict__ ei, int e,
                                          unsigned& r, unsigned& c) {
    if (g_is64) {
        const long long* p = (const long long*)ei;
        r = (unsigned)p[e]; c = (unsigned)p[EE + e];
    } else {
        const int* p = (const int*)ei;
        r = (unsigned)p[e]; c = (unsigned)p[EE + e];
    }
}

// ---------------- dedup: bitmap + small conflict hash --------------------------
__global__ void k_init() {
    int i = blockIdx.x * blockDim.x + threadIdx.x;
    if (i < NN) { g_deg[i] = 1.0f; g_cnt[i] = 0; }
    if (i < HSZ) { g_hkey[i] = HEMPTY; g_hmax[i] = 0; }
    if (i == 0) g_nconf = 0;
}

__global__ void k_mark(const void* __restrict__ ei) {
    int e = blockIdx.x * blockDim.x + threadIdx.x;
    if (e >= EE) return;
    unsigned r, c; load_edge(ei, e, r, c);
    unsigned key = (r << 14) | c;
    unsigned m = 1u << (key & 31);
    unsigned old = atomicOr(&g_bm[key >> 5], m);
    if (old & m) {                                   // duplicate key (rare)
        int p = atomicAdd(&g_nconf, 1);
        if (p < MAXCONF) g_confkey[p] = key;
    }
}

__global__ void k_hbuild() {
    int t = blockIdx.x * blockDim.x + threadIdx.x;
    int n = g_nconf; if (n > MAXCONF) n = MAXCONF;
    if (t >= n) return;
    unsigned key = g_confkey[t];
    unsigned h = hsh(key);
    while (true) {
        unsigned old = atomicCAS(&g_hkey[h], HEMPTY, key);
        if (old == HEMPTY || old == key) break;
        h = (h + 1) & (HSZ - 1);
    }
}

__global__ void k_resolve(const void* __restrict__ ei) {
    int e = blockIdx.x * blockDim.x + threadIdx.x;
    if (e >= EE) return;
    unsigned r, c; load_edge(ei, e, r, c);
    unsigned key = (r << 14) | c;
    unsigned h = hsh(key);
    while (true) {
        unsigned k2 = g_hkey[h];
        if (k2 == HEMPTY) return;                    // not conflicted
        if (k2 == key) { atomicMax(&g_hmax[h], (unsigned)(e + 1)); return; }
        h = (h + 1) & (HSZ - 1);
    }
}

__device__ __forceinline__ bool winner(unsigned key, int e) {
    unsigned h = hsh(key);
    while (true) {
        unsigned k2 = g_hkey[h];
        if (k2 == HEMPTY) return true;
        if (k2 == key) return g_hmax[h] == (unsigned)(e + 1);
        h = (h + 1) & (HSZ - 1);
    }
}

__global__ void k_count(const void* __restrict__ ei, const float* __restrict__ ew) {
    int e = blockIdx.x * blockDim.x + threadIdx.x;
    if (e >= EE) return;
    unsigned r, c; load_edge(ei, e, r, c);
    if (winner((r << 14) | c, e)) {
        atomicAdd(&g_cnt[r], 1);
        atomicAdd(&g_deg[r], ew[e]);
    }
}

__global__ void k_scan() {
    __shared__ int sm[1024];
    int tid = threadIdx.x;
    int base = tid * 16;
    int loc[16];
    int run = 0;
#pragma unroll
    for (int i = 0; i < 16; i++) { loc[i] = run; run += g_cnt[base + i]; }
    sm[tid] = run;
    __syncthreads();
    for (int off = 1; off < 1024; off <<= 1) {
        int v = (tid >= off) ? sm[tid - off] : 0;
        __syncthreads();
        sm[tid] += v;
        __syncthreads();
    }
    int excl = (tid == 0) ? 0 : sm[tid - 1];
#pragma unroll
    for (int i = 0; i < 16; i++) {
        int p = excl + loc[i];
        g_rowptr[base + i] = p;
        g_cursor[base + i] = p;
    }
    if (tid == 1023) g_rowptr[NN] = sm[1023];
}

__global__ void k_fill(const void* __restrict__ ei, const float* __restrict__ ew) {
    int e = blockIdx.x * blockDim.x + threadIdx.x;
    if (e >= EE) return;
    unsigned r, c; load_edge(ei, e, r, c);
    if (winner((r << 14) | c, e)) {
        int p = atomicAdd(&g_cursor[r], 1);
        g_col[p] = (int)c;
        g_wgt[p] = ew[e];
    }
}

// restore bitmap to all-zero for graph replay (sequential 32 MB store)
__global__ void k_clearbm() {
    int i = blockIdx.x * blockDim.x + threadIdx.x;
    uint4 z = make_uint4(0, 0, 0, 0);
    uint4* p = (uint4*)g_bm;
#pragma unroll
    for (int j = 0; j < 4; j++) p[i + j * 524288] = z;   // 4 * 524288 = 2^21 uint4
}

// ---------------- x -> fp16 -----------------------------------------------------
__global__ void k_cvtx(const float* __restrict__ x) {
    int i = blockIdx.x * blockDim.x + threadIdx.x;    // over NN*FIN/2
    float2 v = ((const float2*)x)[i];
    g_xh[i] = __floats2half2_rn(v.x, v.y);
}

// ---------------- SpMM (half gather, fp32 accumulate): warp per row -------------
__device__ __forceinline__ float4 h8_to_f4(uint2 v) {
    __half2 h0 = *(__half2*)&v.x, h1 = *(__half2*)&v.y;
    float2 f0 = __half22float2(h0), f1 = __half22float2(h1);
    return make_float4(f0.x, f0.y, f1.x, f1.y);
}

__global__ void k_spmm1h() {
    int g = blockIdx.x * blockDim.x + threadIdx.x;
    int row = g >> 5, lane = g & 31;
    const uint2* __restrict__ X = (const uint2*)g_xh;   // 32 uint2 per row (128 half)
    float inv = 1.0f / g_deg[row];
    float4 a = h8_to_f4(X[((size_t)row << 5) + lane]);
    float4 acc = make_float4(a.x * inv, a.y * inv, a.z * inv, a.w * inv);
    int s = g_rowptr[row], t = g_rowptr[row + 1];
    for (int j = s; j < t; j++) {
        int   c = __ldg(&g_col[j]);
        float w = __ldg(&g_wgt[j]) * inv;
        float4 v = h8_to_f4(X[((size_t)c << 5) + lane]);
        acc.x += w * v.x; acc.y += w * v.y; acc.z += w * v.z; acc.w += w * v.w;
    }
    ((float4*)g_agg)[((size_t)row << 5) + lane] = acc;
}

__global__ void k_spmm2h(const float* __restrict__ b2, float* __restrict__ outf) {
    int g = blockIdx.x * blockDim.x + threadIdx.x;
    int row = g >> 5, lane = g & 31;
    const uint2* __restrict__ X = (const uint2*)g_zh;
    float inv = 1.0f / g_deg[row];
    float4 a = h8_to_f4(X[((size_t)row << 5) + lane]);
    float4 acc = make_float4(a.x * inv, a.y * inv, a.z * inv, a.w * inv);
    int s = g_rowptr[row], t = g_rowptr[row + 1];
    for (int j = s; j < t; j++) {
        int   c = __ldg(&g_col[j]);
        float w = __ldg(&g_wgt[j]) * inv;
        float4 v = h8_to_f4(X[((size_t)c << 5) + lane]);
        acc.x += w * v.x; acc.y += w * v.y; acc.z += w * v.z; acc.w += w * v.w;
    }
    float4 bb = ((const float4*)b2)[lane];
    acc.x += bb.x; acc.y += bb.y; acc.z += bb.z; acc.w += bb.w;
    ((float4*)outf)[((size_t)row << 5) + lane] = acc;
}

#define COMP(v, kk) ((kk) == 0 ? (v).x : (kk) == 1 ? (v).y : (kk) == 2 ? (v).z : (v).w)

// ---------------- GEMM1 fused: h = relu(LN(agg @ W1 + b1)), f32x2 math ---------
// block: 64 rows x 256 cols, 256 threads, thread tile 8x8 (as 8x4 f32x2 pairs).
#define G1_SMEM ((FIN * FHID + 64 * FIN) * 4)
__global__ void __launch_bounds__(256, 1)
k_g1(const float* __restrict__ W1, const float* __restrict__ b1,
     const float* __restrict__ lng, const float* __restrict__ lnb) {
    extern __shared__ float sm[];
    float4* Bs4 = (float4*)sm;                 // 128x256
    float4* As4 = (float4*)(sm + FIN * FHID);  // 64x128
    const int tid = threadIdx.x;
    const int rbase = blockIdx.x * 64;

    const float4* Wg = (const float4*)W1;
#pragma unroll
    for (int i = 0; i < 32; i++) Bs4[tid + i * 256] = Wg[tid + i * 256];
    const float4* Ag = (const float4*)(g_agg + (size_t)rbase * FIN);
#pragma unroll
    for (int i = 0; i < 8; i++) As4[tid + i * 256] = Ag[tid + i * 256];
    __syncthreads();

    const int cc = tid & 31, rr = tid >> 5;
    u64t acc[8][4];
#pragma unroll
    for (int i = 0; i < 8; i++)
#pragma unroll
        for (int j = 0; j < 4; j++) acc[i][j] = 0ull;

    for (int k4 = 0; k4 < FIN / 4; k4++) {
        float4 av[8];
#pragma unroll
        for (int i = 0; i < 8; i++) av[i] = As4[(rr * 8 + i) * 32 + k4];
#pragma unroll
        for (int kk = 0; kk < 4; kk++) {
            const int k = k4 * 4 + kk;
            float4 b0  = Bs4[k * 64 + cc * 2];
            float4 b1v = Bs4[k * 64 + cc * 2 + 1];
            u64t pb0 = pk2(b0.x,  b0.y),  pb1 = pk2(b0.z,  b0.w);
            u64t pb2 = pk2(b1v.x, b1v.y), pb3 = pk2(b1v.z, b1v.w);
#pragma unroll
            for (int i = 0; i < 8; i++) {
                float a = COMP(av[i], kk);
                u64t pa = pk2(a, a);
                ffma2(acc[i][0], pa, pb0);
                ffma2(acc[i][1], pa, pb1);
                ffma2(acc[i][2], pa, pb2);
                ffma2(acc[i][3], pa, pb3);
            }
        }
    }

    float4 bb0 = ((const float4*)b1)[cc * 2],  bb1 = ((const float4*)b1)[cc * 2 + 1];
    float4 gg0 = ((const float4*)lng)[cc * 2], gg1 = ((const float4*)lng)[cc * 2 + 1];
    float4 nb0 = ((const float4*)lnb)[cc * 2], nb1 = ((const float4*)lnb)[cc * 2 + 1];
    float4* H4 = (float4*)g_h;
#pragma unroll
    for (int i = 0; i < 8; i++) {
        float v0, v1, v2, v3, v4, v5, v6, v7;
        unpk(acc[i][0], v0, v1); unpk(acc[i][1], v2, v3);
        unpk(acc[i][2], v4, v5); unpk(acc[i][3], v6, v7);
        v0 += bb0.x; v1 += bb0.y; v2 += bb0.z; v3 += bb0.w;
        v4 += bb1.x; v5 += bb1.y; v6 += bb1.z; v7 += bb1.w;
        float s = v0 + v1 + v2 + v3 + v4 + v5 + v6 + v7;
        float q = v0 * v0 + v1 * v1 + v2 * v2 + v3 * v3 +
                  v4 * v4 + v5 * v5 + v6 * v6 + v7 * v7;
#pragma unroll
        for (int off = 16; off > 0; off >>= 1) {
            s += __shfl_xor_sync(0xffffffffu, s, off);
            q += __shfl_xor_sync(0xffffffffu, q, off);
        }
        float mu   = s * (1.0f / FHID);
        float var  = q * (1.0f / FHID) - mu * mu;
        float rstd = rsqrtf(var + LN_EPS);
        float o0 = fmaxf((v0 - mu) * rstd * gg0.x + nb0.x, 0.f);
        float o1 = fmaxf((v1 - mu) * rstd * gg0.y + nb0.y, 0.f);
        float o2 = fmaxf((v2 - mu) * rstd * gg0.z + nb0.z, 0.f);
        float o3 = fmaxf((v3 - mu) * rstd * gg0.w + nb0.w, 0.f);
        float o4 = fmaxf((v4 - mu) * rstd * gg1.x + nb1.x, 0.f);
        float o5 = fmaxf((v5 - mu) * rstd * gg1.y + nb1.y, 0.f);
        float o6 = fmaxf((v6 - mu) * rstd * gg1.z + nb1.z, 0.f);
        float o7 = fmaxf((v7 - mu) * rstd * gg1.w + nb1.w, 0.f);
        size_t row = (size_t)(rbase + rr * 8 + i);
        H4[row * 64 + cc * 2]     = make_float4(o0, o1, o2, o3);
        H4[row * 64 + cc * 2 + 1] = make_float4(o4, o5, o6, o7);
    }
}

// ---------------- GEMM2: z = h @ W2 -> fp16 (bias folded into SpMM2) -----------
#define G2_SMEM ((FHID * FOUT + 64 * FHID) * 4)
__global__ void __launch_bounds__(256, 1)
k_g2(const float* __restrict__ W2) {
    extern __shared__ float sm[];
    float4* Bs4 = (float4*)sm;                  // 256x128
    float4* As4 = (float4*)(sm + FHID * FOUT);  // 64x256
    const int tid = threadIdx.x;
    const int rbase = blockIdx.x * 64;

    const float4* Wg = (const float4*)W2;
#pragma unroll
    for (int i = 0; i < 32; i++) Bs4[tid + i * 256] = Wg[tid + i * 256];
    const float4* Hg = (const float4*)(g_h + (size_t)rbase * FHID);
#pragma unroll
    for (int i = 0; i < 16; i++) As4[tid + i * 256] = Hg[tid + i * 256];
    __syncthreads();

    const int cc = tid & 31, rr = tid >> 5;
    u64t acc[8][2];
#pragma unroll
    for (int i = 0; i < 8; i++) { acc[i][0] = 0ull; acc[i][1] = 0ull; }

    for (int k4 = 0; k4 < FHID / 4; k4++) {
        float4 av[8];
#pragma unroll
        for (int i = 0; i < 8; i++) av[i] = As4[(rr * 8 + i) * 64 + k4];
#pragma unroll
        for (int kk = 0; kk < 4; kk++) {
            const int k = k4 * 4 + kk;
            float4 bv = Bs4[k * 32 + cc];
            u64t pb0 = pk2(bv.x, bv.y), pb1 = pk2(bv.z, bv.w);
#pragma unroll
            for (int i = 0; i < 8; i++) {
                float a = COMP(av[i], kk);
                u64t pa = pk2(a, a);
                ffma2(acc[i][0], pa, pb0);
                ffma2(acc[i][1], pa, pb1);
            }
        }
    }

    uint2* Z = (uint2*)g_zh;   // 32 uint2 per row (128 half)
#pragma unroll
    for (int i = 0; i < 8; i++) {
        float v0, v1, v2, v3;
        unpk(acc[i][0], v0, v1); unpk(acc[i][1], v2, v3);
        __half2 h0 = __floats2half2_rn(v0, v1);
        __half2 h1 = __floats2half2_rn(v2, v3);
        uint2 o;
        o.x = *(unsigned*)&h0; o.y = *(unsigned*)&h1;
        size_t row = (size_t)(rbase + rr * 8 + i);
        Z[row * 32 + cc] = o;
    }
}

// ---------------- launch --------------------------------------------------------
extern "C" void kernel_launch(void* const* d_in, const int* in_sizes, int n_in,
                              void* d_out, int out_size) {
    const float* x   = (const float*)d_in[0];
    const void*  ei  = d_in[1];
    const float* ew  = (const float*)d_in[2];
    const float* W1  = (const float*)d_in[3];
    const float* b1  = (const float*)d_in[4];
    const float* W2  = (const float*)d_in[5];
    const float* b2  = (const float*)d_in[6];
    const float* lng = (const float*)d_in[7];
    const float* lnb = (const float*)d_in[8];
    float* out = (float*)d_out;

    cudaFuncSetAttribute(k_g1, cudaFuncAttributeMaxDynamicSharedMemorySize, G1_SMEM);
    cudaFuncSetAttribute(k_g2, cudaFuncAttributeMaxDynamicSharedMemorySize, G2_SMEM);

    k_detect<<<1, 1>>>(ei);
    k_init<<<NN / 256, 256>>>();
    k_mark<<<EE / 256, 256>>>(ei);
    k_hbuild<<<MAXCONF / 256, 256>>>();
    k_resolve<<<EE / 256, 256>>>(ei);
    k_count<<<EE / 256, 256>>>(ei, ew);
    k_scan<<<1, 1024>>>();
    k_fill<<<EE / 256, 256>>>(ei, ew);
    k_clearbm<<<2048, 256>>>();                 // restore bitmap for replay
    k_cvtx<<<(NN * FIN / 2) / 256, 256>>>(x);
    k_spmm1h<<<(NN * 32) / 256, 256>>>();
    k_g1<<<NN / 64, 256, G1_SMEM>>>(W1, b1, lng, lnb);
    k_g2<<<NN / 64, 256, G2_SMEM>>>(W2);
    k_spmm2h<<<(NN * 32) / 256, 256>>>(b2, out);
}

// round 5
// speedup vs baseline: 1.4875x; 1.2793x over previous
#include <cuda_runtime.h>
#include <cuda_fp16.h>

#define NN   16384
#define EE   524288
#define FIN  128
#define FHID 256
#define FOUT 128
#define LN_EPS 1e-5f
#define CAP  192                     // per-row neighbor bucket capacity

#define HBITS 21
#define HSZ   (1u << HBITS)          // 2^21 slots, 16 MB total (L2-resident)
#define HMASK (HSZ - 1)
#define HEMPTY 0xFFFFFFFFu

typedef unsigned long long u64t;

// ---------------- static device scratch ----------------------------------------
__device__ unsigned g_hkey[HSZ];
__device__ unsigned g_hval[HSZ];
__device__ float  g_deg[NN];
__device__ int    g_cnt[NN];
__device__ float2 g_bkt[(size_t)NN * CAP];       // interleaved (bitcast col, weight)
__device__ float  g_agg[(size_t)NN * FIN];
__device__ float  g_h[(size_t)NN * FHID];
__device__ __half2 g_xh[(size_t)NN * FIN / 2];
__device__ __half2 g_zh[(size_t)NN * FOUT / 2];
__device__ int    g_is64;

__device__ __forceinline__ unsigned hsh(unsigned k) {
    return (k * 2654435761u) >> (32 - HBITS);
}

// ---------------- f32x2 packed-FMA helpers -------------------------------------
__device__ __forceinline__ u64t pk2(float x, float y) {
    u64t r;
    asm("mov.b64 %0, {%1, %2};" : "=l"(r) : "r"(__float_as_uint(x)), "r"(__float_as_uint(y)));
    return r;
}
__device__ __forceinline__ void unpk(u64t v, float& x, float& y) {
    unsigned a, b;
    asm("mov.b64 {%0, %1}, %2;" : "=r"(a), "=r"(b) : "l"(v));
    x = __uint_as_float(a); y = __uint_as_float(b);
}
__device__ __forceinline__ void ffma2(u64t& d, u64t a, u64t b) {
    asm("fma.rn.f32x2 %0, %1, %2, %3;" : "=l"(d) : "l"(a), "l"(b), "l"(d));
}

__device__ __forceinline__ void load_edge(const void* __restrict__ ei, int e,
                                          unsigned& r, unsigned& c) {
    if (g_is64) {
        const long long* p = (const long long*)ei;
        r = (unsigned)p[e]; c = (unsigned)p[EE + e];
    } else {
        const int* p = (const int*)ei;
        r = (unsigned)p[e]; c = (unsigned)p[EE + e];
    }
}

// ---------------- fused prep: detect dtype, clear hash, init deg/cnt, x->fp16 --
// grid 4096 x 256 = 1,048,576 threads
__global__ void k_prep(const float* __restrict__ x, const void* __restrict__ ei) {
    int i = blockIdx.x * blockDim.x + threadIdx.x;
    // x -> half2 (NN*FIN/2 = 1,048,576 elements)
    float2 v = ((const float2*)x)[i];
    g_xh[i] = __floats2half2_rn(v.x, v.y);
    // clear hash: hkey as uint4 (HSZ/4 = 524288), hval likewise
    if (i < (HSZ / 4)) {
        ((uint4*)g_hkey)[i] = make_uint4(HEMPTY, HEMPTY, HEMPTY, HEMPTY);
        ((uint4*)g_hval)[i] = make_uint4(0, 0, 0, 0);
    }
    if (i < NN) { g_deg[i] = 1.0f; g_cnt[i] = 0; }
    if (i == 0) {
        const int* p = (const int*)ei;
        int o = 0;
#pragma unroll
        for (int j = 0; j < 64; j++) o |= p[2 * j + 1];
        g_is64 = (o == 0) ? 1 : 0;
    }
}

// ---------------- pass 1: hash insert, last(max)-index-wins per key ------------
__global__ void k_insert(const void* __restrict__ ei) {
    int e = blockIdx.x * blockDim.x + threadIdx.x;
    if (e >= EE) return;
    unsigned r, c; load_edge(ei, e, r, c);
    unsigned key = (r << 14) | c;
    unsigned h = hsh(key);
    while (true) {
        unsigned old = atomicCAS(&g_hkey[h], HEMPTY, key);
        if (old == HEMPTY || old == key) break;
        h = (h + 1) & HMASK;
    }
    atomicMax(&g_hval[h], (unsigned)(e + 1));
}

// ---------------- pass 2: winners fill per-row buckets + degree ----------------
__global__ void k_fillb(const void* __restrict__ ei, const float* __restrict__ ew) {
    int e = blockIdx.x * blockDim.x + threadIdx.x;
    if (e >= EE) return;
    unsigned r, c; load_edge(ei, e, r, c);
    unsigned key = (r << 14) | c;
    unsigned h = hsh(key);
    while (g_hkey[h] != key) h = (h + 1) & HMASK;   // key guaranteed present
    if (g_hval[h] == (unsigned)(e + 1)) {
        float w = ew[e];
        int slot = atomicAdd(&g_cnt[r], 1);
        if (slot < CAP) {
            float2 cw; cw.x = __uint_as_float(c); cw.y = w;
            g_bkt[(size_t)r * CAP + slot] = cw;
        }
        atomicAdd(&g_deg[r], w);
    }
}

// ---------------- SpMM (half gather, fp32 accumulate): warp per row ------------
__device__ __forceinline__ float4 h8_to_f4(uint2 v) {
    __half2 h0 = *(__half2*)&v.x, h1 = *(__half2*)&v.y;
    float2 f0 = __half22float2(h0), f1 = __half22float2(h1);
    return make_float4(f0.x, f0.y, f1.x, f1.y);
}

__global__ void k_spmm1h() {
    int g = blockIdx.x * blockDim.x + threadIdx.x;
    int row = g >> 5, lane = g & 31;
    const uint2* __restrict__ X = (const uint2*)g_xh;
    float inv = 1.0f / g_deg[row];
    float4 a = h8_to_f4(X[((size_t)row << 5) + lane]);
    float4 acc = make_float4(a.x * inv, a.y * inv, a.z * inv, a.w * inv);
    int n = g_cnt[row]; if (n > CAP) n = CAP;
    const float2* __restrict__ B = g_bkt + (size_t)row * CAP;
#pragma unroll 4
    for (int j = 0; j < n; j++) {
        float2 cw = __ldg(&B[j]);
        unsigned c = __float_as_uint(cw.x);
        float    w = cw.y * inv;
        float4 v = h8_to_f4(X[((size_t)c << 5) + lane]);
        acc.x += w * v.x; acc.y += w * v.y; acc.z += w * v.z; acc.w += w * v.w;
    }
    ((float4*)g_agg)[((size_t)row << 5) + lane] = acc;
}

__global__ void k_spmm2h(const float* __restrict__ b2, float* __restrict__ outf) {
    int g = blockIdx.x * blockDim.x + threadIdx.x;
    int row = g >> 5, lane = g & 31;
    const uint2* __restrict__ X = (const uint2*)g_zh;
    float inv = 1.0f / g_deg[row];
    float4 a = h8_to_f4(X[((size_t)row << 5) + lane]);
    float4 acc = make_float4(a.x * inv, a.y * inv, a.z * inv, a.w * inv);
    int n = g_cnt[row]; if (n > CAP) n = CAP;
    const float2* __restrict__ B = g_bkt + (size_t)row * CAP;
#pragma unroll 4
    for (int j = 0; j < n; j++) {
        float2 cw = __ldg(&B[j]);
        unsigned c = __float_as_uint(cw.x);
        float    w = cw.y * inv;
        float4 v = h8_to_f4(X[((size_t)c << 5) + lane]);
        acc.x += w * v.x; acc.y += w * v.y; acc.z += w * v.z; acc.w += w * v.w;
    }
    float4 bb = ((const float4*)b2)[lane];
    acc.x += bb.x; acc.y += bb.y; acc.z += bb.z; acc.w += bb.w;
    ((float4*)outf)[((size_t)row << 5) + lane] = acc;
}

#define COMP(v, kk) ((kk) == 0 ? (v).x : (kk) == 1 ? (v).y : (kk) == 2 ? (v).z : (v).w)

// ---------------- GEMM1 fused: h = relu(LN(agg @ W1 + b1)), f32x2 math ---------
#define G1_SMEM ((FIN * FHID + 64 * FIN) * 4)
__global__ void __launch_bounds__(256, 1)
k_g1(const float* __restrict__ W1, const float* __restrict__ b1,
     const float* __restrict__ lng, const float* __restrict__ lnb) {
    extern __shared__ float sm[];
    float4* Bs4 = (float4*)sm;                 // 128x256
    float4* As4 = (float4*)(sm + FIN * FHID);  // 64x128
    const int tid = threadIdx.x;
    const int rbase = blockIdx.x * 64;

    const float4* Wg = (const float4*)W1;
#pragma unroll
    for (int i = 0; i < 32; i++) Bs4[tid + i * 256] = Wg[tid + i * 256];
    const float4* Ag = (const float4*)(g_agg + (size_t)rbase * FIN);
#pragma unroll
    for (int i = 0; i < 8; i++) As4[tid + i * 256] = Ag[tid + i * 256];
    __syncthreads();

    const int cc = tid & 31, rr = tid >> 5;
    u64t acc[8][4];
#pragma unroll
    for (int i = 0; i < 8; i++)
#pragma unroll
        for (int j = 0; j < 4; j++) acc[i][j] = 0ull;

    for (int k4 = 0; k4 < FIN / 4; k4++) {
        float4 av[8];
#pragma unroll
        for (int i = 0; i < 8; i++) av[i] = As4[(rr * 8 + i) * 32 + k4];
#pragma unroll
        for (int kk = 0; kk < 4; kk++) {
            const int k = k4 * 4 + kk;
            float4 b0  = Bs4[k * 64 + cc * 2];
            float4 b1v = Bs4[k * 64 + cc * 2 + 1];
            u64t pb0 = pk2(b0.x,  b0.y),  pb1 = pk2(b0.z,  b0.w);
            u64t pb2 = pk2(b1v.x, b1v.y), pb3 = pk2(b1v.z, b1v.w);
#pragma unroll
            for (int i = 0; i < 8; i++) {
                float a = COMP(av[i], kk);
                u64t pa = pk2(a, a);
                ffma2(acc[i][0], pa, pb0);
                ffma2(acc[i][1], pa, pb1);
                ffma2(acc[i][2], pa, pb2);
                ffma2(acc[i][3], pa, pb3);
            }
        }
    }

    float4 bb0 = ((const float4*)b1)[cc * 2],  bb1 = ((const float4*)b1)[cc * 2 + 1];
    float4 gg0 = ((const float4*)lng)[cc * 2], gg1 = ((const float4*)lng)[cc * 2 + 1];
    float4 nb0 = ((const float4*)lnb)[cc * 2], nb1 = ((const float4*)lnb)[cc * 2 + 1];
    float4* H4 = (float4*)g_h;
#pragma unroll
    for (int i = 0; i < 8; i++) {
        float v0, v1, v2, v3, v4, v5, v6, v7;
        unpk(acc[i][0], v0, v1); unpk(acc[i][1], v2, v3);
        unpk(acc[i][2], v4, v5); unpk(acc[i][3], v6, v7);
        v0 += bb0.x; v1 += bb0.y; v2 += bb0.z; v3 += bb0.w;
        v4 += bb1.x; v5 += bb1.y; v6 += bb1.z; v7 += bb1.w;
        float s = v0 + v1 + v2 + v3 + v4 + v5 + v6 + v7;
        float q = v0 * v0 + v1 * v1 + v2 * v2 + v3 * v3 +
                  v4 * v4 + v5 * v5 + v6 * v6 + v7 * v7;
#pragma unroll
        for (int off = 16; off > 0; off >>= 1) {
            s += __shfl_xor_sync(0xffffffffu, s, off);
            q += __shfl_xor_sync(0xffffffffu, q, off);
        }
        float mu   = s * (1.0f / FHID);
        float var  = q * (1.0f / FHID) - mu * mu;
        float rstd = rsqrtf(var + LN_EPS);
        float o0 = fmaxf((v0 - mu) * rstd * gg0.x + nb0.x, 0.f);
        float o1 = fmaxf((v1 - mu) * rstd * gg0.y + nb0.y, 0.f);
        float o2 = fmaxf((v2 - mu) * rstd * gg0.z + nb0.z, 0.f);
        float o3 = fmaxf((v3 - mu) * rstd * gg0.w + nb0.w, 0.f);
        float o4 = fmaxf((v4 - mu) * rstd * gg1.x + nb1.x, 0.f);
        float o5 = fmaxf((v5 - mu) * rstd * gg1.y + nb1.y, 0.f);
        float o6 = fmaxf((v6 - mu) * rstd * gg1.z + nb1.z, 0.f);
        float o7 = fmaxf((v7 - mu) * rstd * gg1.w + nb1.w, 0.f);
        size_t row = (size_t)(rbase + rr * 8 + i);
        H4[row * 64 + cc * 2]     = make_float4(o0, o1, o2, o3);
        H4[row * 64 + cc * 2 + 1] = make_float4(o4, o5, o6, o7);
    }
}

// ---------------- GEMM2: z = h @ W2 -> fp16 (bias folded into SpMM2) -----------
#define G2_SMEM ((FHID * FOUT + 64 * FHID) * 4)
__global__ void __launch_bounds__(256, 1)
k_g2(const float* __restrict__ W2) {
    extern __shared__ float sm[];
    float4* Bs4 = (float4*)sm;                  // 256x128
    float4* As4 = (float4*)(sm + FHID * FOUT);  // 64x256
    const int tid = threadIdx.x;
    const int rbase = blockIdx.x * 64;

    const float4* Wg = (const float4*)W2;
#pragma unroll
    for (int i = 0; i < 32; i++) Bs4[tid + i * 256] = Wg[tid + i * 256];
    const float4* Hg = (const float4*)(g_h + (size_t)rbase * FHID);
#pragma unroll
    for (int i = 0; i < 16; i++) As4[tid + i * 256] = Hg[tid + i * 256];
    __syncthreads();

    const int cc = tid & 31, rr = tid >> 5;
    u64t acc[8][2];
#pragma unroll
    for (int i = 0; i < 8; i++) { acc[i][0] = 0ull; acc[i][1] = 0ull; }

    for (int k4 = 0; k4 < FHID / 4; k4++) {
        float4 av[8];
#pragma unroll
        for (int i = 0; i < 8; i++) av[i] = As4[(rr * 8 + i) * 64 + k4];
#pragma unroll
        for (int kk = 0; kk < 4; kk++) {
            const int k = k4 * 4 + kk;
            float4 bv = Bs4[k * 32 + cc];
            u64t pb0 = pk2(bv.x, bv.y), pb1 = pk2(bv.z, bv.w);
#pragma unroll
            for (int i = 0; i < 8; i++) {
                float a = COMP(av[i], kk);
                u64t pa = pk2(a, a);
                ffma2(acc[i][0], pa, pb0);
                ffma2(acc[i][1], pa, pb1);
            }
        }
    }

    uint2* Z = (uint2*)g_zh;
#pragma unroll
    for (int i = 0; i < 8; i++) {
        float v0, v1, v2, v3;
        unpk(acc[i][0], v0, v1); unpk(acc[i][1], v2, v3);
        __half2 h0 = __floats2half2_rn(v0, v1);
        __half2 h1 = __floats2half2_rn(v2, v3);
        uint2 o;
        o.x = *(unsigned*)&h0; o.y = *(unsigned*)&h1;
        size_t row = (size_t)(rbase + rr * 8 + i);
        Z[row * 32 + cc] = o;
    }
}

// ---------------- launch --------------------------------------------------------
extern "C" void kernel_launch(void* const* d_in, const int* in_sizes, int n_in,
                              void* d_out, int out_size) {
    const float* x   = (const float*)d_in[0];
    const void*  ei  = d_in[1];
    const float* ew  = (const float*)d_in[2];
    const float* W1  = (const float*)d_in[3];
    const float* b1  = (const float*)d_in[4];
    const float* W2  = (const float*)d_in[5];
    const float* b2  = (const float*)d_in[6];
    const float* lng = (const float*)d_in[7];
    const float* lnb = (const float*)d_in[8];
    float* out = (float*)d_out;

    cudaFuncSetAttribute(k_g1, cudaFuncAttributeMaxDynamicSharedMemorySize, G1_SMEM);
    cudaFuncSetAttribute(k_g2, cudaFuncAttributeMaxDynamicSharedMemorySize, G2_SMEM);

    k_prep<<<4096, 256>>>(x, ei);
    k_insert<<<EE / 256, 256>>>(ei);
    k_fillb<<<EE / 256, 256>>>(ei, ew);
    k_spmm1h<<<(NN * 32) / 256, 256>>>();
    k_g1<<<NN / 64, 256, G1_SMEM>>>(W1, b1, lng, lnb);
    k_g2<<<NN / 64, 256, G2_SMEM>>>(W2);
    k_spmm2h<<<(NN * 32) / 256, 256>>>(b2, out);
}

// round 6
// speedup vs baseline: 1.5831x; 1.0643x over previous
#include <cuda_runtime.h>
#include <cuda_fp16.h>

#define NN   16384
#define EE   524288
#define FIN  128
#define FHID 256
#define FOUT 128
#define LN_EPS 1e-5f
#define CAP  192

#define HBITS 21
#define HSZ   (1u << HBITS)
#define HMASK (HSZ - 1)
#define HEMPTY 0xFFFFFFFFu

typedef unsigned long long u64t;

// ---------------- static device scratch ----------------------------------------
__device__ unsigned g_hkey[HSZ];
__device__ unsigned g_hval[HSZ];
__device__ float  g_deg[NN];
__device__ int    g_cnt[NN];
__device__ float2 g_bkt[(size_t)NN * CAP];       // interleaved (bitcast col, weight)
__device__ float  g_agg[(size_t)NN * FIN];
__device__ float  g_h[(size_t)NN * FHID];
__device__ __half2 g_xh[(size_t)NN * FIN / 2];
__device__ __half2 g_zh[(size_t)NN * FOUT / 2];
__device__ int    g_is64;

__device__ __forceinline__ unsigned hsh(unsigned k) {
    return (k * 2654435761u) >> (32 - HBITS);
}

// ---------------- f32x2 packed-FMA helpers -------------------------------------
__device__ __forceinline__ u64t pk2(float x, float y) {
    u64t r;
    asm("mov.b64 %0, {%1, %2};" : "=l"(r) : "r"(__float_as_uint(x)), "r"(__float_as_uint(y)));
    return r;
}
__device__ __forceinline__ void unpk(u64t v, float& x, float& y) {
    unsigned a, b;
    asm("mov.b64 {%0, %1}, %2;" : "=r"(a), "=r"(b) : "l"(v));
    x = __uint_as_float(a); y = __uint_as_float(b);
}
__device__ __forceinline__ void ffma2(u64t& d, u64t a, u64t b) {
    asm("fma.rn.f32x2 %0, %1, %2, %3;" : "=l"(d) : "l"(a), "l"(b), "l"(d));
}

__device__ __forceinline__ void load_edge(const void* __restrict__ ei, int e,
                                          unsigned& r, unsigned& c) {
    if (g_is64) {
        const long long* p = (const long long*)ei;
        r = (unsigned)p[e]; c = (unsigned)p[EE + e];
    } else {
        const int* p = (const int*)ei;
        r = (unsigned)p[e]; c = (unsigned)p[EE + e];
    }
}

// ---------------- fused prep: detect dtype, clear hash, init deg/cnt, x->fp16 --
__global__ void k_prep(const float* __restrict__ x, const void* __restrict__ ei) {
    int i = blockIdx.x * blockDim.x + threadIdx.x;
    float2 v = ((const float2*)x)[i];
    g_xh[i] = __floats2half2_rn(v.x, v.y);
    if (i < (HSZ / 4)) {
        ((uint4*)g_hkey)[i] = make_uint4(HEMPTY, HEMPTY, HEMPTY, HEMPTY);
        ((uint4*)g_hval)[i] = make_uint4(0, 0, 0, 0);
    }
    if (i < NN) { g_deg[i] = 1.0f; g_cnt[i] = 0; }
    if (i == 0) {
        const int* p = (const int*)ei;
        int o = 0;
#pragma unroll
        for (int j = 0; j < 64; j++) o |= p[2 * j + 1];
        g_is64 = (o == 0) ? 1 : 0;
    }
}

// ---------------- pass 1: hash insert, last(max)-index-wins per key ------------
__global__ void k_insert(const void* __restrict__ ei) {
    int e = blockIdx.x * blockDim.x + threadIdx.x;
    if (e >= EE) return;
    unsigned r, c; load_edge(ei, e, r, c);
    unsigned key = (r << 14) | c;
    unsigned h = hsh(key);
    while (true) {
        unsigned old = atomicCAS(&g_hkey[h], HEMPTY, key);
        if (old == HEMPTY || old == key) break;
        h = (h + 1) & HMASK;
    }
    atomicMax(&g_hval[h], (unsigned)(e + 1));
}

// ---------------- pass 2: scan hash slots; each occupied slot = one winner -----
__global__ void k_fillscan(const float* __restrict__ ew) {
    unsigned i = blockIdx.x * blockDim.x + threadIdx.x;   // over HSZ
    unsigned key = g_hkey[i];
    if (key == HEMPTY) return;
    unsigned e = g_hval[i] - 1u;
    unsigned r = key >> 14, c = key & 0x3FFFu;
    float w = __ldg(&ew[e]);
    int slot = atomicAdd(&g_cnt[r], 1);
    if (slot < CAP) {
        float2 cw; cw.x = __uint_as_float(c); cw.y = w;
        g_bkt[(size_t)r * CAP + slot] = cw;
    }
    atomicAdd(&g_deg[r], w);
}

// ---------------- SpMM (half gather, fp32 accumulate): warp per row ------------
__device__ __forceinline__ float4 h8_to_f4(uint2 v) {
    __half2 h0 = *(__half2*)&v.x, h1 = *(__half2*)&v.y;
    float2 f0 = __half22float2(h0), f1 = __half22float2(h1);
    return make_float4(f0.x, f0.y, f1.x, f1.y);
}

// core gather: acc = x_self + sum w_j * X[c_j]; inv applied at the end
__device__ __forceinline__ float4 gather_row(const uint2* __restrict__ X,
                                             int row, int lane) {
    float4 acc = h8_to_f4(__ldg(&X[((unsigned)row << 5) + lane]));
    int n = g_cnt[row]; if (n > CAP) n = CAP;
    const float4* __restrict__ B4 = (const float4*)(g_bkt + (size_t)row * CAP);
    int t4 = n >> 2;
    for (int t = 0; t < t4; t++) {
        float4 p = __ldg(&B4[2 * t]);
        float4 q = __ldg(&B4[2 * t + 1]);
        unsigned c0 = __float_as_uint(p.x), c1 = __float_as_uint(p.z);
        unsigned c2 = __float_as_uint(q.x), c3 = __float_as_uint(q.z);
        uint2 v0 = __ldg(&X[(c0 << 5) + lane]);
        uint2 v1 = __ldg(&X[(c1 << 5) + lane]);
        uint2 v2 = __ldg(&X[(c2 << 5) + lane]);
        uint2 v3 = __ldg(&X[(c3 << 5) + lane]);
        float4 f0 = h8_to_f4(v0), f1 = h8_to_f4(v1);
        float4 f2 = h8_to_f4(v2), f3 = h8_to_f4(v3);
        acc.x += p.y * f0.x; acc.y += p.y * f0.y; acc.z += p.y * f0.z; acc.w += p.y * f0.w;
        acc.x += p.w * f1.x; acc.y += p.w * f1.y; acc.z += p.w * f1.z; acc.w += p.w * f1.w;
        acc.x += q.y * f2.x; acc.y += q.y * f2.y; acc.z += q.y * f2.z; acc.w += q.y * f2.w;
        acc.x += q.w * f3.x; acc.y += q.w * f3.y; acc.z += q.w * f3.z; acc.w += q.w * f3.w;
    }
    const float2* __restrict__ B2 = (const float2*)B4;
    for (int j = t4 * 4; j < n; j++) {
        float2 cw = __ldg(&B2[j]);
        unsigned c = __float_as_uint(cw.x);
        float4 v = h8_to_f4(__ldg(&X[(c << 5) + lane]));
        acc.x += cw.y * v.x; acc.y += cw.y * v.y;
        acc.z += cw.y * v.z; acc.w += cw.y * v.w;
    }
    return acc;
}

__global__ void k_spmm1h() {
    int g = blockIdx.x * blockDim.x + threadIdx.x;
    int row = g >> 5, lane = g & 31;
    float4 acc = gather_row((const uint2*)g_xh, row, lane);
    float inv = 1.0f / g_deg[row];
    acc.x *= inv; acc.y *= inv; acc.z *= inv; acc.w *= inv;
    ((float4*)g_agg)[((size_t)row << 5) + lane] = acc;
}

__global__ void k_spmm2h(const float* __restrict__ b2, float* __restrict__ outf) {
    int g = blockIdx.x * blockDim.x + threadIdx.x;
    int row = g >> 5, lane = g & 31;
    float4 acc = gather_row((const uint2*)g_zh, row, lane);
    float inv = 1.0f / g_deg[row];
    float4 bb = ((const float4*)b2)[lane];
    acc.x = acc.x * inv + bb.x; acc.y = acc.y * inv + bb.y;
    acc.z = acc.z * inv + bb.z; acc.w = acc.w * inv + bb.w;
    ((float4*)outf)[((size_t)row << 5) + lane] = acc;
}

#define COMP(v, kk) ((kk) == 0 ? (v).x : (kk) == 1 ? (v).y : (kk) == 2 ? (v).z : (v).w)

// ---------------- GEMM1 fused: h = relu(LN(agg @ W1 + b1)), f32x2 math ---------
#define G1_SMEM ((FIN * FHID + 64 * FIN) * 4)
__global__ void __launch_bounds__(256, 1)
k_g1(const float* __restrict__ W1, const float* __restrict__ b1,
     const float* __restrict__ lng, const float* __restrict__ lnb) {
    extern __shared__ float sm[];
    float4* Bs4 = (float4*)sm;                 // 128x256
    float4* As4 = (float4*)(sm + FIN * FHID);  // 64x128
    const int tid = threadIdx.x;
    const int rbase = blockIdx.x * 64;

    const float4* Wg = (const float4*)W1;
#pragma unroll
    for (int i = 0; i < 32; i++) Bs4[tid + i * 256] = Wg[tid + i * 256];
    const float4* Ag = (const float4*)(g_agg + (size_t)rbase * FIN);
#pragma unroll
    for (int i = 0; i < 8; i++) As4[tid + i * 256] = Ag[tid + i * 256];
    __syncthreads();

    const int cc = tid & 31, rr = tid >> 5;
    u64t acc[8][4];
#pragma unroll
    for (int i = 0; i < 8; i++)
#pragma unroll
        for (int j = 0; j < 4; j++) acc[i][j] = 0ull;

    for (int k4 = 0; k4 < FIN / 4; k4++) {
        float4 av[8];
#pragma unroll
        for (int i = 0; i < 8; i++) av[i] = As4[(rr * 8 + i) * 32 + k4];
#pragma unroll
        for (int kk = 0; kk < 4; kk++) {
            const int k = k4 * 4 + kk;
            float4 b0  = Bs4[k * 64 + cc * 2];
            float4 b1v = Bs4[k * 64 + cc * 2 + 1];
            u64t pb0 = pk2(b0.x,  b0.y),  pb1 = pk2(b0.z,  b0.w);
            u64t pb2 = pk2(b1v.x, b1v.y), pb3 = pk2(b1v.z, b1v.w);
#pragma unroll
            for (int i = 0; i < 8; i++) {
                float a = COMP(av[i], kk);
                u64t pa = pk2(a, a);
                ffma2(acc[i][0], pa, pb0);
                ffma2(acc[i][1], pa, pb1);
                ffma2(acc[i][2], pa, pb2);
                ffma2(acc[i][3], pa, pb3);
            }
        }
    }

    float4 bb0 = ((const float4*)b1)[cc * 2],  bb1 = ((const float4*)b1)[cc * 2 + 1];
    float4 gg0 = ((const float4*)lng)[cc * 2], gg1 = ((const float4*)lng)[cc * 2 + 1];
    float4 nb0 = ((const float4*)lnb)[cc * 2], nb1 = ((const float4*)lnb)[cc * 2 + 1];
    float4* H4 = (float4*)g_h;
#pragma unroll
    for (int i = 0; i < 8; i++) {
        float v0, v1, v2, v3, v4, v5, v6, v7;
        unpk(acc[i][0], v0, v1); unpk(acc[i][1], v2, v3);
        unpk(acc[i][2], v4, v5); unpk(acc[i][3], v6, v7);
        v0 += bb0.x; v1 += bb0.y; v2 += bb0.z; v3 += bb0.w;
        v4 += bb1.x; v5 += bb1.y; v6 += bb1.z; v7 += bb1.w;
        float s = v0 + v1 + v2 + v3 + v4 + v5 + v6 + v7;
        float q = v0 * v0 + v1 * v1 + v2 * v2 + v3 * v3 +
                  v4 * v4 + v5 * v5 + v6 * v6 + v7 * v7;
#pragma unroll
        for (int off = 16; off > 0; off >>= 1) {
            s += __shfl_xor_sync(0xffffffffu, s, off);
            q += __shfl_xor_sync(0xffffffffu, q, off);
        }
        float mu   = s * (1.0f / FHID);
        float var  = q * (1.0f / FHID) - mu * mu;
        float rstd = rsqrtf(var + LN_EPS);
        float o0 = fmaxf((v0 - mu) * rstd * gg0.x + nb0.x, 0.f);
        float o1 = fmaxf((v1 - mu) * rstd * gg0.y + nb0.y, 0.f);
        float o2 = fmaxf((v2 - mu) * rstd * gg0.z + nb0.z, 0.f);
        float o3 = fmaxf((v3 - mu) * rstd * gg0.w + nb0.w, 0.f);
        float o4 = fmaxf((v4 - mu) * rstd * gg1.x + nb1.x, 0.f);
        float o5 = fmaxf((v5 - mu) * rstd * gg1.y + nb1.y, 0.f);
        float o6 = fmaxf((v6 - mu) * rstd * gg1.z + nb1.z, 0.f);
        float o7 = fmaxf((v7 - mu) * rstd * gg1.w + nb1.w, 0.f);
        size_t row = (size_t)(rbase + rr * 8 + i);
        H4[row * 64 + cc * 2]     = make_float4(o0, o1, o2, o3);
        H4[row * 64 + cc * 2 + 1] = make_float4(o4, o5, o6, o7);
    }
}

// ---------------- GEMM2: z = h @ W2 -> fp16 (bias folded into SpMM2) -----------
#define G2_SMEM ((FHID * FOUT + 64 * FHID) * 4)
__global__ void __launch_bounds__(256, 1)
k_g2(const float* __restrict__ W2) {
    extern __shared__ float sm[];
    float4* Bs4 = (float4*)sm;                  // 256x128
    float4* As4 = (float4*)(sm + FHID * FOUT);  // 64x256
    const int tid = threadIdx.x;
    const int rbase = blockIdx.x * 64;

    const float4* Wg = (const float4*)W2;
#pragma unroll
    for (int i = 0; i < 32; i++) Bs4[tid + i * 256] = Wg[tid + i * 256];
    const float4* Hg = (const float4*)(g_h + (size_t)rbase * FHID);
#pragma unroll
    for (int i = 0; i < 16; i++) As4[tid + i * 256] = Hg[tid + i * 256];
    __syncthreads();

    const int cc = tid & 31, rr = tid >> 5;
    u64t acc[8][2];
#pragma unroll
    for (int i = 0; i < 8; i++) { acc[i][0] = 0ull; acc[i][1] = 0ull; }

    for (int k4 = 0; k4 < FHID / 4; k4++) {
        float4 av[8];
#pragma unroll
        for (int i = 0; i < 8; i++) av[i] = As4[(rr * 8 + i) * 64 + k4];
#pragma unroll
        for (int kk = 0; kk < 4; kk++) {
            const int k = k4 * 4 + kk;
            float4 bv = Bs4[k * 32 + cc];
            u64t pb0 = pk2(bv.x, bv.y), pb1 = pk2(bv.z, bv.w);
#pragma unroll
            for (int i = 0; i < 8; i++) {
                float a = COMP(av[i], kk);
                u64t pa = pk2(a, a);
                ffma2(acc[i][0], pa, pb0);
                ffma2(acc[i][1], pa, pb1);
            }
        }
    }

    uint2* Z = (uint2*)g_zh;
#pragma unroll
    for (int i = 0; i < 8; i++) {
        float v0, v1, v2, v3;
        unpk(acc[i][0], v0, v1); unpk(acc[i][1], v2, v3);
        __half2 h0 = __floats2half2_rn(v0, v1);
        __half2 h1 = __floats2half2_rn(v2, v3);
        uint2 o;
        o.x = *(unsigned*)&h0; o.y = *(unsigned*)&h1;
        size_t row = (size_t)(rbase + rr * 8 + i);
        Z[row * 32 + cc] = o;
    }
}

// ---------------- launch --------------------------------------------------------
extern "C" void kernel_launch(void* const* d_in, const int* in_sizes, int n_in,
                              void* d_out, int out_size) {
    const float* x   = (const float*)d_in[0];
    const void*  ei  = d_in[1];
    const float* ew  = (const float*)d_in[2];
    const float* W1  = (const float*)d_in[3];
    const float* b1  = (const float*)d_in[4];
    const float* W2  = (const float*)d_in[5];
    const float* b2  = (const float*)d_in[6];
    const float* lng = (const float*)d_in[7];
    const float* lnb = (const float*)d_in[8];
    float* out = (float*)d_out;

    cudaFuncSetAttribute(k_g1, cudaFuncAttributeMaxDynamicSharedMemorySize, G1_SMEM);
    cudaFuncSetAttribute(k_g2, cudaFuncAttributeMaxDynamicSharedMemorySize, G2_SMEM);

    k_prep<<<4096, 256>>>(x, ei);
    k_insert<<<EE / 256, 256>>>(ei);
    k_fillscan<<<HSZ / 256, 256>>>(ew);
    k_spmm1h<<<(NN * 32) / 256, 256>>>();
    k_g1<<<NN / 64, 256, G1_SMEM>>>(W1, b1, lng, lnb);
    k_g2<<<NN / 64, 256, G2_SMEM>>>(W2);
    k_spmm2h<<<(NN * 32) / 256, 256>>>(b2, out);
}